// round 10
// baseline (speedup 1.0000x reference)
#include <cuda_runtime.h>
#include <math.h>
#include <stdint.h>

// Problem constants
#define BQ    512
#define EDIM  512
#define CDIM  70722
#define TWC   (2*CDIM)
#define EPSF  0.001f
#define HF    0.333f
#define SF    64.0f
#define MMARG 0.4f
#define TALPHA 1.0f

// GEMM tile config
#define BM 128
#define BN 128
#define BK 32
#define NCH (EDIM/BK)               // 16 chunks
#define ARS 520                     // A smem row stride in halves (1040B)
#define BRS 40                      // B smem row stride in halves (80B)
#define A_BYTES  (BM*ARS*2)         // 133120
#define B_TILE   (BN*BRS*2)         // 10240
#define B_OFF    A_BYTES
#define SSQP_OFF (B_OFF + 2*B_TILE)        // 153600
#define SINV_OFF (SSQP_OFF + 512*4)        // 155648
#define SMEM_SZ  (SINV_OFF + BN*4)         // 156160

// Scratch
__device__ float d_gang[BQ];
__device__ float d_gadd[BQ];

// ============================ helpers ======================================
__device__ __forceinline__ uint32_t smem_u32(const void* p) {
    uint32_t a;
    asm("{ .reg .u64 t; cvta.to.shared.u64 t, %1; cvt.u32.u64 %0, t; }" : "=r"(a) : "l"(p));
    return a;
}
__device__ __forceinline__ void ldsm4(uint32_t* r, uint32_t addr) {
    asm volatile("ldmatrix.sync.aligned.m8n8.x4.shared.b16 {%0,%1,%2,%3}, [%4];"
        : "=r"(r[0]), "=r"(r[1]), "=r"(r[2]), "=r"(r[3]) : "r"(addr));
}
__device__ __forceinline__ void mma_f16(float* c, const uint32_t* a, const uint32_t* b) {
    asm volatile(
        "mma.sync.aligned.m16n8k16.row.col.f32.f16.f16.f32 "
        "{%0,%1,%2,%3}, {%4,%5,%6,%7}, {%8,%9}, {%0,%1,%2,%3};"
        : "+f"(c[0]), "+f"(c[1]), "+f"(c[2]), "+f"(c[3])
        : "r"(a[0]), "r"(a[1]), "r"(a[2]), "r"(a[3]), "r"(b[0]), "r"(b[1]));
}
__device__ __forceinline__ uint32_t pack_f16(float x0, float x1) {
    uint32_t p;
    asm("cvt.rn.f16x2.f32 %0, %1, %2;" : "=r"(p) : "f"(x1), "f"(x0));
    return p;
}

// ---------------------------------------------------------------------------
// K3: batch statistics + cw_margin output
// ---------------------------------------------------------------------------
__global__ void stats_kernel(const float* __restrict__ norms,
                             const int*   __restrict__ label,
                             float* __restrict__ out) {
    __shared__ float sn[BQ];
    __shared__ int   lab[BQ];
    __shared__ float red[BQ];
    int t = threadIdx.x;
    float x = fminf(fmaxf(norms[t], 0.001f), 100.0f);
    sn[t] = x; lab[t] = label[t]; red[t] = x;
    __syncthreads();
    for (int o = 256; o > 0; o >>= 1) { if (t < o) red[t] += red[t+o]; __syncthreads(); }
    float mean = red[0] * (1.0f / BQ);
    __syncthreads();
    float d = x - mean;
    red[t] = d * d;
    __syncthreads();
    for (int o = 256; o > 0; o >>= 1) { if (t < o) red[t] += red[t+o]; __syncthreads(); }
    float stdv = sqrtf(red[0] / (float)(BQ - 1));
    float batch_mean = mean * TALPHA + (1.0f - TALPHA) * 20.0f;
    float batch_std  = stdv * TALPHA + (1.0f - TALPHA) * 10.0f;
    int ml = lab[t];
    float s = 0.f; int cnt = 0;
    for (int j = 0; j < BQ; ++j) if (lab[j] == ml) { s += sn[j]; cnt++; }
    float cwm = (s / (float)cnt) * TALPHA + (1.0f - TALPHA) * 20.0f;
    float inv = 1.0f / (batch_std + EPSF);
    float ms = fminf(fmaxf((x - batch_mean) * inv * HF, -1.0f), 1.0f);
    d_gang[t] = -MMARG * ms;
    d_gadd[t] =  MMARG + MMARG * ms;
    out[(size_t)2 * BQ * CDIM + t] = fminf(fmaxf((x - cwm) * inv, -1.0f), 1.0f) * HF;
}

// ---------------------------------------------------------------------------
// K4: fp16 mma.sync GEMM. A resident in smem (FULL 128x512 tile); B with
// distance-2 prefetch, double-buffered. 512 threads, 16 warps (4m x 4n).
// ---------------------------------------------------------------------------
__global__ void __launch_bounds__(512, 1)
gemm_kernel(const float* __restrict__ A,       // emb [512,512]
            const float* __restrict__ Kn,      // kernel t=0 plane (stride TWC)
            float* __restrict__ out) {
    extern __shared__ char smem[];
    const uint32_t sb = smem_u32(smem);
    float* ssqp = (float*)(smem + SSQP_OFF);
    float* sinv = (float*)(smem + SINV_OFF);

    const int t = threadIdx.x;
    const int lane = t & 31;
    const int wid = t >> 5;
    const int mbase = blockIdx.x * BM;
    const int cbase = blockIdx.y * BN;
    const int wm = (wid >> 2) * 32;
    const int wn = (wid & 3) * 32;

    float acc[2][4][4];
    #pragma unroll
    for (int i = 0; i < 2; ++i)
        #pragma unroll
        for (int j = 0; j < 4; ++j)
            #pragma unroll
            for (int r = 0; r < 4; ++r) acc[i][j][r] = 0.f;

    // ---- A prologue: convert whole 128x512 tile to fp16, resident ----
    // 128 rows x 128 float4 = 16384 float4; 512 threads x 32 iterations.
    {
        uint16_t* Ah = (uint16_t*)smem;
        #pragma unroll
        for (int i = 0; i < 32; ++i) {
            int u = t + i * 512;            // 0..16383
            int m = u >> 7, q = u & 127;    // m: row, q: float4 index within row
            float4 v = *(const float4*)&A[(size_t)(mbase + m) * EDIM + q * 4];
            *(uint2*)&Ah[m * ARS + q * 4] =
                make_uint2(pack_f16(v.x, v.y), pack_f16(v.z, v.w));
        }
    }

    // B-load mapping: column bn, 8 k's per thread
    const int bn  = t & 127;
    const int bkh = (t >> 7) * 8;
    const int bc  = cbase + bn;
    const bool bvalid = bc < CDIM;
    float ssq = 0.f;

    // ldmatrix lane addressing
    const int a_row  = wm + (lane & 15);
    const int a_coff = (lane >> 4) * 8;
    const int b_n    = wn + ((lane >> 4) << 3) + (lane & 7);
    const int b_koff = ((lane >> 3) & 1) * 8;

    // distance-2 prefetch registers
    float bpre[2][8];
    #pragma unroll
    for (int j = 0; j < 8; ++j) {
        bpre[0][j] = bvalid ? Kn[(size_t)(bkh + j) * TWC + bc] : 0.f;
        bpre[1][j] = bvalid ? Kn[(size_t)(BK + bkh + j) * TWC + bc] : 0.f;
    }

    for (int ch = 0; ch < NCH; ++ch) {
        const int cur = ch & 1;

        // ---- convert prefetched chunk into its buffer ----
        {
            uint16_t* Bh = (uint16_t*)(smem + B_OFF + cur * B_TILE);
            #pragma unroll
            for (int j = 0; j < 8; j += 2) {
                float v0 = bpre[cur][j], v1 = bpre[cur][j+1];
                ssq += v0 * v0 + v1 * v1;
                *(uint32_t*)&Bh[bn * BRS + bkh + j] = pack_f16(v0, v1);
            }
        }
        __syncthreads();

        // ---- issue loads for chunk ch+2 into the slot just consumed ----
        if (ch + 2 < NCH) {
            const int kb = (ch + 2) * BK;
            #pragma unroll
            for (int j = 0; j < 8; ++j)
                bpre[cur][j] = bvalid ? Kn[(size_t)(kb + bkh + j) * TWC + bc] : 0.f;
        }

        // ---- math on current B buffer + resident A ----
        const uint32_t aH = sb;
        const uint32_t bH = sb + B_OFF + cur * B_TILE;
        #pragma unroll
        for (int kf = 0; kf < 2; ++kf) {
            const int kc = ch * BK + kf * 16;     // global k for A
            uint32_t ah[2][4], bhf[4][2];
            #pragma unroll
            for (int mf = 0; mf < 2; ++mf) {
                uint32_t ad = ((uint32_t)((a_row + mf * 16) * ARS + kc + a_coff)) * 2;
                ldsm4(ah[mf], aH + ad);
            }
            {
                const int kcl = kf * 16;          // local k for B
                uint32_t bd0 = ((uint32_t)(b_n * BRS + kcl + b_koff)) * 2;
                uint32_t bd1 = ((uint32_t)((b_n + 16) * BRS + kcl + b_koff)) * 2;
                uint32_t r[4];
                ldsm4(r, bH + bd0);
                bhf[0][0]=r[0]; bhf[0][1]=r[1]; bhf[1][0]=r[2]; bhf[1][1]=r[3];
                ldsm4(r, bH + bd1);
                bhf[2][0]=r[0]; bhf[2][1]=r[1]; bhf[3][0]=r[2]; bhf[3][1]=r[3];
            }
            #pragma unroll
            for (int mf = 0; mf < 2; ++mf)
                #pragma unroll
                for (int nf = 0; nf < 4; ++nf)
                    mma_f16(acc[mf][nf], ah[mf], bhf[nf]);
        }
        __syncthreads();
    }

    // ---- column inverse norms (fp32-exact) ----
    ssqp[t] = ssq;
    __syncthreads();
    if (t < 128)
        sinv[t] = rsqrtf(ssqp[t] + ssqp[t + 128] + ssqp[t + 256] + ssqp[t + 384]);
    __syncthreads();

    // ---- epilogue: clip*scale, dual-plane float2 stores ----
    const float lo = -1.0f + EPSF, hi = 1.0f - EPSF;
    float inv[4][2];
    #pragma unroll
    for (int nf = 0; nf < 4; ++nf) {
        int c0 = wn + nf * 8 + (lane & 3) * 2;
        inv[nf][0] = sinv[c0];
        inv[nf][1] = sinv[c0 + 1];
    }
    #pragma unroll
    for (int mf = 0; mf < 2; ++mf) {
        int row0 = mbase + wm + mf * 16 + (lane >> 2);
        #pragma unroll
        for (int nf = 0; nf < 4; ++nf) {
            int col = cbase + wn + nf * 8 + (lane & 3) * 2;
            if (col < CDIM) {
                float v0 = fminf(fmaxf(acc[mf][nf][0] * inv[nf][0], lo), hi) * SF;
                float v1 = fminf(fmaxf(acc[mf][nf][1] * inv[nf][1], lo), hi) * SF;
                float v2 = fminf(fmaxf(acc[mf][nf][2] * inv[nf][0], lo), hi) * SF;
                float v3 = fminf(fmaxf(acc[mf][nf][3] * inv[nf][1], lo), hi) * SF;
                size_t o0 = (size_t)row0 * CDIM + col;
                size_t o1 = (size_t)(row0 + 8) * CDIM + col;
                *(float2*)(out + o0) = make_float2(v0, v1);
                *(float2*)(out + o1) = make_float2(v2, v3);
                *(float2*)(out + (size_t)BQ * CDIM + o0) = make_float2(v0, v1);
                *(float2*)(out + (size_t)BQ * CDIM + o1) = make_float2(v2, v3);
            }
        }
    }
}

// ---------------------------------------------------------------------------
// K5: label-column fixup (merged cos2; fp32-exact)
// ---------------------------------------------------------------------------
__global__ void fixup_kernel(const float* __restrict__ kern,
                             const float* __restrict__ emb,
                             const int*   __restrict__ label,
                             float* __restrict__ out) {
    int b = blockIdx.x, t = threadIdx.x;
    int lab = label[b];
    const float* col0 = kern + lab;                  // t=0 plane
    const float* col1 = kern + (size_t)CDIM + lab;   // t=1 plane
    float dt0 = 0.f, ss0 = 0.f, dt1 = 0.f, ss1 = 0.f;
    for (int e = t; e < EDIM; e += 128) {
        float a = emb[b * EDIM + e];
        float v0 = col0[(size_t)e * TWC];
        float v1 = col1[(size_t)e * TWC];
        dt0 += a * v0; ss0 += v0 * v0;
        dt1 += a * v1; ss1 += v1 * v1;
    }
    __shared__ float s0[128], s1[128], s2[128], s3[128];
    s0[t] = dt0; s1[t] = ss0; s2[t] = dt1; s3[t] = ss1;
    __syncthreads();
    for (int o = 64; o > 0; o >>= 1) {
        if (t < o) { s0[t]+=s0[t+o]; s1[t]+=s1[t+o]; s2[t]+=s2[t+o]; s3[t]+=s3[t+o]; }
        __syncthreads();
    }
    if (t == 0) {
        const float lo = -1.0f + EPSF, hi = 1.0f - EPSF;
        const float thlo = EPSF, thhi = (float)M_PI - EPSF;
        float gang = d_gang[b], gadd = d_gadd[b];
        float w1 = s0[0] * rsqrtf(s1[0]);
        w1 = fminf(fmaxf(w1, lo), hi);
        float th1 = fminf(fmaxf(acosf(w1) + gang, thlo), thhi);
        out[(size_t)b * CDIM + lab] = (cosf(th1) - gadd) * SF;
        float w2 = s2[0] * rsqrtf(s3[0]);
        w2 = fminf(fmaxf(w2, lo), hi);
        float th2 = fminf(fmaxf(acosf(w2) + gang, thlo), thhi);
        out[(size_t)BQ * CDIM + (size_t)b * CDIM + lab] = (cosf(th2) - gadd) * SF;
    }
}

// ---------------------------------------------------------------------------
extern "C" void kernel_launch(void* const* d_in, const int* in_sizes, int n_in,
                              void* d_out, int out_size) {
    const float* emb   = (const float*)d_in[0];  // [512, 512]
    const float* norms = (const float*)d_in[1];  // [512, 1]
    const int*   label = (const int*)  d_in[2];  // [512]
    const float* kern  = (const float*)d_in[3];  // [512, 2, 70722]
    float* out = (float*)d_out;

    cudaFuncSetAttribute(gemm_kernel,
                         cudaFuncAttributeMaxDynamicSharedMemorySize, SMEM_SZ);

    stats_kernel<<<1, BQ>>>(norms, label, out);
    gemm_kernel<<<dim3(4, (CDIM + BN - 1) / BN), 512, SMEM_SZ>>>(emb, kern, out);
    fixup_kernel<<<BQ, 128>>>(kern, emb, label, out);
}